// round 14
// baseline (speedup 1.0000x reference)
#include <cuda_runtime.h>
#include <cuda_fp16.h>
#include <cstdint>

#define CH 256
#define NMAX 200000
#define KOFF 27
#define PATHS 4
#define NPK (KOFF * PATHS)
#define CS_TILES 175   // >= ceil(max non-center cnt / 128); loop handles overflow

// Scratch (device globals: no allocation allowed in kernel_launch)
__device__ __half g_H16[(size_t)NMAX * CH];  // lifted features, fp16
__device__ float g_A[(size_t)NMAX * CH];     // conv result (fp32)
__device__ float g_sum[CH];
__device__ float g_sumsq[CH];
__device__ float g_scale[CH];
__device__ float g_shift[CH];
__device__ __half g_Wlh[65536];              // Wl fp16, transposed [n=p*64+d][k=c]
__device__ __half g_W2h[65536];              // W2 fp16, transposed [n][k]
__device__ __half g_Wch[442368];             // Wc fp16, transposed [pk][d][c]
__device__ int   g_cnt[NPK];                 // valid pair count per (p,k)

// ---------------------------------------------------------------------------
// fp16 MMA, fp32 accumulate: A row-major 16x16, B col-major 16x8
__device__ __forceinline__ void mma_f16(float c[4], uint32_t a0, uint32_t a1,
                                        uint32_t a2, uint32_t a3,
                                        uint32_t b0, uint32_t b1) {
    asm volatile(
        "mma.sync.aligned.m16n8k16.row.col.f32.f16.f16.f32 "
        "{%0,%1,%2,%3}, {%4,%5,%6,%7}, {%8,%9}, {%0,%1,%2,%3};\n"
        : "+f"(c[0]), "+f"(c[1]), "+f"(c[2]), "+f"(c[3])
        : "r"(a0), "r"(a1), "r"(a2), "r"(a3), "r"(b0), "r"(b1));
}

__device__ __forceinline__ uint32_t smem_u32(const void* p) {
    return (uint32_t)__cvta_generic_to_shared(p);
}
__device__ __forceinline__ void cp16(uint32_t dst, const void* src, int sz) {
    asm volatile("cp.async.cg.shared.global [%0], [%1], 16, %2;"
                 :: "r"(dst), "l"(src), "r"(sz));
}
__device__ __forceinline__ void cp_commit() { asm volatile("cp.async.commit_group;"); }
template <int N> __device__ __forceinline__ void cp_wait() {
    asm volatile("cp.async.wait_group %0;" :: "n"(N));
}
__device__ __forceinline__ void red_v4(float* dst, float4 v) {
    asm volatile("red.global.add.v4.f32 [%0], {%1,%2,%3,%4};"
                 :: "l"(dst), "f"(v.x), "f"(v.y), "f"(v.z), "f"(v.w) : "memory");
}

// ---------------------------------------------------------------------------
__global__ void prep_weights(const float* __restrict__ Wl,
                             const float* __restrict__ W2,
                             const float* __restrict__ Wc) {
    int i = blockIdx.x * 256 + threadIdx.x;
    if (i < 65536) {
        // Wl [P][256][64] -> g_Wlh [n=p*64+d][k=c]
        int p = i >> 14, c = (i >> 6) & 255, d = i & 63;
        g_Wlh[(p * 64 + d) * 256 + c] = __float2half(Wl[i]);
    } else if (i < 131072) {
        // W2 [256][256] (k,n) -> g_W2h [n][k]
        int j = i - 65536;
        int k = j >> 8, nn = j & 255;
        g_W2h[nn * 256 + k] = __float2half(W2[j]);
    } else if (i < 131072 + 442368) {
        int j = i - 131072;
        int pk = j >> 12, r = j & 4095, d = r >> 6, c = r & 63;
        g_Wch[j] = __float2half(Wc[(size_t)pk * 4096 + c * 64 + d]);  // transpose
    }
}

// Valid pairs per (p,k) are a prefix -> binary search the boundary.
__global__ void count_pairs(const int* __restrict__ in_idx, int n, int M) {
    int pk = threadIdx.x;
    if (pk >= NPK) return;
    const int* a = in_idx + (size_t)pk * M;
    int lo = 0, hi = M;
    while (lo < hi) {
        int mid = (lo + hi) >> 1;
        if (__ldg(&a[mid]) < n) lo = mid + 1; else hi = mid;
    }
    g_cnt[pk] = lo;
}

// ---------------------------------------------------------------------------
// H = fp16round(x @ Wl_cat + bl).  fp16 MMA; tile 128x64, BK=16, 2-stage
// pipeline.  grid (4, rows): 32-reg acc -> 4 CTA/SM for more MLP.
__global__ __launch_bounds__(256) void gemm_h(const float* __restrict__ x,
                                              const float* __restrict__ bl, int n) {
    __shared__ __align__(16) __half As[2][128][24];   // [m][k]
    __shared__ __align__(16) __half Bt[2][64][24];    // [n][k]
    const int colBase = blockIdx.x * 64;
    const int rowBase = blockIdx.y * 128;
    const int tid = threadIdx.x;
    const int warpId = tid >> 5, lane = tid & 31;
    const int grp = lane >> 2, qp = lane & 3;
    const int wm = (warpId & 3) * 32, wn = (warpId >> 2) * 32;

    float acc[2][4][4];
#pragma unroll
    for (int mt = 0; mt < 2; mt++)
#pragma unroll
        for (int nt = 0; nt < 4; nt++)
#pragma unroll
            for (int r = 0; r < 4; r++) acc[mt][nt][r] = 0.f;

    float4 ar[2];
    int arow[2], akq[2];
#pragma unroll
    for (int i = 0; i < 2; i++) { int ci = tid + i * 256; arow[i] = ci >> 2; akq[i] = ci & 3; }

#define LOAD_A(kt) do {                                                        \
    _Pragma("unroll")                                                          \
    for (int i = 0; i < 2; i++) {                                              \
        int gr = rowBase + arow[i];                                            \
        ar[i] = (gr < n) ? *(const float4*)&x[(size_t)gr * CH + (kt) * 16 + akq[i] * 4] \
                         : make_float4(0.f, 0.f, 0.f, 0.f);                    \
    } } while (0)
#define STS_A(b) do {                                                          \
    _Pragma("unroll")                                                          \
    for (int i = 0; i < 2; i++) {                                              \
        float4 v = ar[i];                                                      \
        *(__half2*)&As[b][arow[i]][akq[i] * 4]     = __floats2half2_rn(v.x, v.y); \
        *(__half2*)&As[b][arow[i]][akq[i] * 4 + 2] = __floats2half2_rn(v.z, v.w); \
    } } while (0)
#define LOAD_B(kt, b) do {                                                     \
    if (tid < 128) {                                                           \
        int col_ = tid >> 1, q_ = tid & 1;                                     \
        cp16(smem_u32(&Bt[b][col_][q_ * 8]),                                   \
             &g_Wlh[(size_t)(colBase + col_) * 256 + (kt) * 16 + q_ * 8], 16); \
    }                                                                          \
    cp_commit(); } while (0)
#define COMPUTE(b) do {                                                        \
    uint32_t af[2][4], bf[4][2];                                               \
    _Pragma("unroll")                                                          \
    for (int mt = 0; mt < 2; mt++) {                                           \
        int r0 = wm + mt * 16 + grp;                                           \
        af[mt][0] = *(const uint32_t*)&As[b][r0][qp * 2];                      \
        af[mt][1] = *(const uint32_t*)&As[b][r0 + 8][qp * 2];                  \
        af[mt][2] = *(const uint32_t*)&As[b][r0][qp * 2 + 8];                  \
        af[mt][3] = *(const uint32_t*)&As[b][r0 + 8][qp * 2 + 8];              \
    }                                                                          \
    _Pragma("unroll")                                                          \
    for (int nt = 0; nt < 4; nt++) {                                           \
        int c0 = wn + nt * 8 + grp;                                            \
        bf[nt][0] = *(const uint32_t*)&Bt[b][c0][qp * 2];                      \
        bf[nt][1] = *(const uint32_t*)&Bt[b][c0][qp * 2 + 8];                  \
    }                                                                          \
    _Pragma("unroll")                                                          \
    for (int mt = 0; mt < 2; mt++)                                             \
        _Pragma("unroll")                                                      \
        for (int nt = 0; nt < 4; nt++)                                         \
            mma_f16(acc[mt][nt], af[mt][0], af[mt][1], af[mt][2], af[mt][3],   \
                    bf[nt][0], bf[nt][1]);                                     \
    } while (0)

    LOAD_B(0, 0);
    LOAD_B(1, 1);
    LOAD_A(0); STS_A(0); LOAD_A(1);
    cp_wait<1>(); __syncthreads();
    for (int kt = 0; kt < 16; kt++) {
        int b = kt & 1;
        if (kt + 1 < 16) STS_A(b ^ 1);
        if (kt + 2 < 16) LOAD_A(kt + 2);
        COMPUTE(b);
        if (kt + 1 < 16) cp_wait<0>();
        __syncthreads();
        if (kt + 2 < 16) LOAD_B(kt + 2, b);
    }
#undef LOAD_A
#undef STS_A
#undef LOAD_B
#undef COMPUTE

#pragma unroll
    for (int mt = 0; mt < 2; mt++) {
#pragma unroll
        for (int nt = 0; nt < 4; nt++) {
            int col = colBase + wn + nt * 8 + qp * 2;
            float b0 = bl[col], b1 = bl[col + 1];
            int gr0 = rowBase + wm + mt * 16 + grp;
            if (gr0 < n) {
                __half2 h = __floats2half2_rn(acc[mt][nt][0] + b0, acc[mt][nt][1] + b1);
                *(__half2*)&g_H16[(size_t)gr0 * CH + col] = h;
            }
            int gr1 = gr0 + 8;
            if (gr1 < n) {
                __half2 h = __floats2half2_rn(acc[mt][nt][2] + b0, acc[mt][nt][3] + b1);
                *(__half2*)&g_H16[(size_t)gr1 * CH + col] = h;
            }
        }
    }
}

// ---------------------------------------------------------------------------
// Center offset (k=13): identity pairs, covers ALL rows.  fp16 gather +
// m16n8k16 fp16 MMA, fp32 staging, plain coalesced stores (initializes g_A).
__global__ __launch_bounds__(256) void conv_center(int n) {
    __shared__ __align__(16) char sm[32768];
    __half (*Gs)[72] = (__half(*)[72])sm;            // [128][72] halves
    __half (*Wt)[72] = (__half(*)[72])(sm + 18432);  // [64][72] halves (transposed W)
    float* Stg = (float*)sm;                         // phase 2: [128][64] floats
    const int p = blockIdx.y;
    const int r0b = blockIdx.x * 128;
    const int tid = threadIdx.x;

    {   // weights: 64 rows x 128B
        const __half* Wpk = g_Wch + (size_t)(p * KOFF + 13) * 4096;
#pragma unroll
        for (int i = 0; i < 2; i++) {
            int ci = tid + i * 256;
            int d = ci >> 3, q = ci & 7;
            cp16(smem_u32(&Wt[d][q * 8]), &Wpk[d * 64 + q * 8], 16);
        }
    }
    {   // gather (identity): 128 rows x 128B
        int m = tid >> 1, half_ = tid & 1;
        int gr = r0b + m;
        int sz = (gr < n) ? 16 : 0;
        const __half* hp = &g_H16[(size_t)(gr < n ? gr : 0) * CH + p * 64 + half_ * 32];
#pragma unroll
        for (int q = 0; q < 4; q++)
            cp16(smem_u32(&Gs[m][half_ * 32 + q * 8]), hp + q * 8, sz);
    }
    cp_commit(); cp_wait<0>(); __syncthreads();

    const int warpId = tid >> 5, lane = tid & 31;
    const int grp = lane >> 2, qp = lane & 3;
    const int wm = (warpId & 3) * 32, wn = (warpId >> 2) * 32;

    float acc[2][4][4];
#pragma unroll
    for (int mt = 0; mt < 2; mt++)
#pragma unroll
        for (int nt = 0; nt < 4; nt++)
#pragma unroll
            for (int r = 0; r < 4; r++) acc[mt][nt][r] = 0.f;

#pragma unroll
    for (int c8 = 0; c8 < 4; c8++) {
        int kk0 = c8 * 16;
        uint32_t af[2][4], bf[4][2];
#pragma unroll
        for (int mt = 0; mt < 2; mt++) {
            int r = wm + mt * 16 + grp;
            af[mt][0] = *(const uint32_t*)&Gs[r][kk0 + qp * 2];
            af[mt][1] = *(const uint32_t*)&Gs[r + 8][kk0 + qp * 2];
            af[mt][2] = *(const uint32_t*)&Gs[r][kk0 + qp * 2 + 8];
            af[mt][3] = *(const uint32_t*)&Gs[r + 8][kk0 + qp * 2 + 8];
        }
#pragma unroll
        for (int nt = 0; nt < 4; nt++) {
            int c0 = wn + nt * 8 + grp;
            bf[nt][0] = *(const uint32_t*)&Wt[c0][kk0 + qp * 2];
            bf[nt][1] = *(const uint32_t*)&Wt[c0][kk0 + qp * 2 + 8];
        }
#pragma unroll
        for (int mt = 0; mt < 2; mt++)
#pragma unroll
            for (int nt = 0; nt < 4; nt++)
                mma_f16(acc[mt][nt], af[mt][0], af[mt][1], af[mt][2], af[mt][3],
                        bf[nt][0], bf[nt][1]);
    }
    __syncthreads();                 // Gs/Wt dead -> reuse as Stg

#pragma unroll
    for (int mt = 0; mt < 2; mt++)
#pragma unroll
        for (int nt = 0; nt < 4; nt++) {
            int col = wn + nt * 8 + qp * 2;
            int rw = wm + mt * 16 + grp;
            int sw = (rw & 7) << 2;  // same for rw and rw+8
            *(float2*)&Stg[rw * 64 + (col ^ sw)] =
                make_float2(acc[mt][nt][0], acc[mt][nt][1]);
            *(float2*)&Stg[(rw + 8) * 64 + (col ^ sw)] =
                make_float2(acc[mt][nt][2], acc[mt][nt][3]);
        }
    __syncthreads();

#pragma unroll
    for (int i = 0; i < 8; i++) {
        int idx = tid + i * 256;
        int row = idx >> 4, c4 = idx & 15;
        int gr = r0b + row;
        if (gr < n) {
            float4 v = *(const float4*)&Stg[row * 64 + ((c4 * 4) ^ ((row & 7) << 2))];
            *(float4*)&g_A[(size_t)gr * CH + p * 64 + c4 * 4] = v;
        }
    }
}

// ---------------------------------------------------------------------------
// Sparse conv over the 26 non-center offsets: fp16 gather + fp16 MMA,
// lane-pair shuffle -> red.global.add.v4.f32 scatter (half the RED ops).
__global__ __launch_bounds__(256) void conv_scatter(const int* __restrict__ in_idx,
                                                    const int* __restrict__ out_idx,
                                                    int M) {
    __shared__ __align__(16) __half Gs[128][72];
    __shared__ __align__(16) __half Wt[64][72];
    __shared__ int Os[128];
    const int p = blockIdx.z;
    const int ky = blockIdx.y;
    const int k = ky + (ky >= 13);  // skip center
    const int pk = p * KOFF + k;
    const int cnt = g_cnt[pk];
    const int tid = threadIdx.x;
    if (blockIdx.x * 128 >= cnt) return;

    {   // weights once per block (joins first gather's commit group)
        const __half* Wpk = g_Wch + (size_t)pk * 4096;
#pragma unroll
        for (int i = 0; i < 2; i++) {
            int ci = tid + i * 256;
            int d = ci >> 3, q = ci & 7;
            cp16(smem_u32(&Wt[d][q * 8]), &Wpk[d * 64 + q * 8], 16);
        }
    }

    const int warpId = tid >> 5, lane = tid & 31;
    const int grp = lane >> 2, qp = lane & 3;
    const int wm = (warpId & 3) * 32, wn = (warpId >> 2) * 32;

    for (int base0 = blockIdx.x * 128; base0 < cnt; base0 += gridDim.x * 128) {
        int rem = cnt - base0; if (rem > 128) rem = 128;
        const size_t base = (size_t)pk * M + base0;

        {
            int m = tid >> 1, half_ = tid & 1;
            int jm = (m < rem) ? __ldg(&in_idx[base + m]) : 0;
            int sz = (m < rem) ? 16 : 0;   // sz=0 -> cp.async zero-fills
            const __half* hp = &g_H16[(size_t)jm * CH + p * 64 + half_ * 32];
#pragma unroll
            for (int q = 0; q < 4; q++)
                cp16(smem_u32(&Gs[m][half_ * 32 + q * 8]), hp + q * 8, sz);
            if (half_ == 0)
                Os[m] = (m < rem) ? __ldg(&out_idx[base + m]) : -1;
        }
        cp_commit(); cp_wait<0>(); __syncthreads();

        float acc[2][4][4];
#pragma unroll
        for (int mt = 0; mt < 2; mt++)
#pragma unroll
            for (int nt = 0; nt < 4; nt++)
#pragma unroll
                for (int r = 0; r < 4; r++) acc[mt][nt][r] = 0.f;

#pragma unroll
        for (int c8 = 0; c8 < 4; c8++) {
            int kk0 = c8 * 16;
            uint32_t af[2][4], bf[4][2];
#pragma unroll
            for (int mt = 0; mt < 2; mt++) {
                int r = wm + mt * 16 + grp;
                af[mt][0] = *(const uint32_t*)&Gs[r][kk0 + qp * 2];
                af[mt][1] = *(const uint32_t*)&Gs[r + 8][kk0 + qp * 2];
                af[mt][2] = *(const uint32_t*)&Gs[r][kk0 + qp * 2 + 8];
                af[mt][3] = *(const uint32_t*)&Gs[r + 8][kk0 + qp * 2 + 8];
            }
#pragma unroll
            for (int nt = 0; nt < 4; nt++) {
                int c0 = wn + nt * 8 + grp;
                bf[nt][0] = *(const uint32_t*)&Wt[c0][kk0 + qp * 2];
                bf[nt][1] = *(const uint32_t*)&Wt[c0][kk0 + qp * 2 + 8];
            }
#pragma unroll
            for (int mt = 0; mt < 2; mt++)
#pragma unroll
                for (int nt = 0; nt < 4; nt++)
                    mma_f16(acc[mt][nt], af[mt][0], af[mt][1], af[mt][2], af[mt][3],
                            bf[nt][0], bf[nt][1]);
        }

        // Lane-pair shuffle -> v4 RED scatter (even-qp lanes issue)
#pragma unroll
        for (int mt = 0; mt < 2; mt++) {
            int r = wm + mt * 16 + grp;
            int o0 = Os[r], o1 = Os[r + 8];
#pragma unroll
            for (int nt = 0; nt < 4; nt++) {
                float a0 = acc[mt][nt][0], a1 = acc[mt][nt][1];
                float a2 = acc[mt][nt][2], a3 = acc[mt][nt][3];
                float p0 = __shfl_xor_sync(0xffffffffu, a0, 1);
                float p1 = __shfl_xor_sync(0xffffffffu, a1, 1);
                float p2 = __shfl_xor_sync(0xffffffffu, a2, 1);
                float p3 = __shfl_xor_sync(0xffffffffu, a3, 1);
                if ((qp & 1) == 0) {
                    int col = p * 64 + wn + nt * 8 + qp * 2;  // 16B-aligned
                    if (o0 >= 0)
                        red_v4(&g_A[(size_t)o0 * CH + col], make_float4(a0, a1, p0, p1));
                    if (o1 >= 0)
                        red_v4(&g_A[(size_t)o1 * CH + col], make_float4(a2, a3, p2, p3));
                }
            }
        }
        __syncthreads();            // Gs/Os reusable for next tile
    }
}

// ---------------------------------------------------------------------------
__global__ __launch_bounds__(256) void bn_stats(int n) {
    __shared__ float4 rs[4][64], rq[4][64];
    int tid = threadIdx.x;
    int cq = tid & 63;
    int rl = tid >> 6;
    float4 s = make_float4(0.f, 0.f, 0.f, 0.f);
    float4 s2 = make_float4(0.f, 0.f, 0.f, 0.f);
#pragma unroll 8
    for (int r = blockIdx.x * 4 + rl; r < n; r += gridDim.x * 4) {
        float4 v = *(const float4*)&g_A[(size_t)r * CH + cq * 4];
        s.x += v.x; s.y += v.y; s.z += v.z; s.w += v.w;
        s2.x += v.x * v.x; s2.y += v.y * v.y; s2.z += v.z * v.z; s2.w += v.w * v.w;
    }
    rs[rl][cq] = s; rq[rl][cq] = s2;
    __syncthreads();
    if (rl == 0) {
#pragma unroll
        for (int i = 1; i < 4; i++) {
            float4 a = rs[i][cq], b = rq[i][cq];
            s.x += a.x; s.y += a.y; s.z += a.z; s.w += a.w;
            s2.x += b.x; s2.y += b.y; s2.z += b.z; s2.w += b.w;
        }
        int c = cq * 4;
        atomicAdd(&g_sum[c + 0], s.x);  atomicAdd(&g_sum[c + 1], s.y);
        atomicAdd(&g_sum[c + 2], s.z);  atomicAdd(&g_sum[c + 3], s.w);
        atomicAdd(&g_sumsq[c + 0], s2.x); atomicAdd(&g_sumsq[c + 1], s2.y);
        atomicAdd(&g_sumsq[c + 2], s2.z); atomicAdd(&g_sumsq[c + 3], s2.w);
    }
}

__global__ void bn_finalize(const float* __restrict__ gamma,
                            const float* __restrict__ beta, int n) {
    int j = threadIdx.x;
    float inv = 1.f / (float)n;
    float mu = g_sum[j] * inv;
    float var = g_sumsq[j] * inv - mu * mu;
    float sc = gamma[j] * rsqrtf(var + 1e-5f);
    g_scale[j] = sc;
    g_shift[j] = beta[j] - mu * sc;
}

// ---------------------------------------------------------------------------
// out = relu(bn(A)) @ W2 + b2 + x.  fp16 MMA; tile 128x64, grid (4, rows);
// bn+relu+fp16 fused into A staging.
__global__ __launch_bounds__(256) void gemm_out(const float* __restrict__ b2,
                                                const float* __restrict__ x,
                                                float* __restrict__ out, int n) {
    __shared__ __align__(16) __half As[2][128][24];
    __shared__ __align__(16) __half Bt[2][64][24];
    __shared__ float sc[256], sh[256];
    const int colBase = blockIdx.x * 64;
    const int rowBase = blockIdx.y * 128;
    const int tid = threadIdx.x;
    const int warpId = tid >> 5, lane = tid & 31;
    const int grp = lane >> 2, qp = lane & 3;
    const int wm = (warpId & 3) * 32, wn = (warpId >> 2) * 32;

    sc[tid] = g_scale[tid];
    sh[tid] = g_shift[tid];

    float acc[2][4][4];
#pragma unroll
    for (int mt = 0; mt < 2; mt++)
#pragma unroll
        for (int nt = 0; nt < 4; nt++)
#pragma unroll
            for (int r = 0; r < 4; r++) acc[mt][nt][r] = 0.f;

    float4 ar[2];
    int arow[2], akq[2];
#pragma unroll
    for (int i = 0; i < 2; i++) { int ci = tid + i * 256; arow[i] = ci >> 2; akq[i] = ci & 3; }

#define LOAD_A(kt) do {                                                        \
    _Pragma("unroll")                                                          \
    for (int i = 0; i < 2; i++) {                                              \
        int gr = rowBase + arow[i];                                            \
        ar[i] = (gr < n) ? *(const float4*)&g_A[(size_t)gr * CH + (kt) * 16 + akq[i] * 4] \
                         : make_float4(0.f, 0.f, 0.f, 0.f);                    \
    } } while (0)
#define STS_A(b, kt) do {                                                      \
    _Pragma("unroll")                                                          \
    for (int i = 0; i < 2; i++) {                                              \
        float4 v = ar[i];                                                      \
        int c0 = (kt) * 16 + akq[i] * 4;                                       \
        v.x = fmaxf(v.x * sc[c0 + 0] + sh[c0 + 0], 0.f);                       \
        v.y = fmaxf(v.y * sc[c0 + 1] + sh[c0 + 1], 0.f);                       \
        v.z = fmaxf(v.z * sc[c0 + 2] + sh[c0 + 2], 0.f);                       \
        v.w = fmaxf(v.w * sc[c0 + 3] + sh[c0 + 3], 0.f);                       \
        *(__half2*)&As[b][arow[i]][akq[i] * 4]     = __floats2half2_rn(v.x, v.y); \
        *(__half2*)&As[b][arow[i]][akq[i] * 4 + 2] = __floats2half2_rn(v.z, v.w); \
    } } while (0)
#define LOAD_B(kt, b) do {                                                     \
    if (tid < 128) {                                                           \
        int col_ = tid >> 1, q_ = tid & 1;                                     \
        cp16(smem_u32(&Bt[b][col_][q_ * 8]),                                   \
             &g_W2h[(size_t)(colBase + col_) * 256 + (kt) * 16 + q_ * 8], 16); \
    }                                                                          \
    cp_commit(); } while (0)
#define COMPUTE(b) do {                                                        \
    uint32_t af[2][4], bf[4][2];                                               \
    _Pragma("unroll")                                                          \
    for (int mt = 0; mt < 2; mt++) {                                           \
        int r0 = wm + mt * 16 + grp;                                           \
        af[mt][0] = *(const uint32_t*)&As[b][r0][qp * 2];                      \
        af[mt][1] = *(const uint32_t*)&As[b][r0 + 8][qp * 2];                  \
        af[mt][2] = *(const uint32_t*)&As[b][r0][qp * 2 + 8];                  \
        af[mt][3] = *(const uint32_t*)&As[b][r0 + 8][qp * 2 + 8];              \
    }                                                                          \
    _Pragma("unroll")                                                          \
    for (int nt = 0; nt < 4; nt++) {                                           \
        int c0 = wn + nt * 8 + grp;                                            \
        bf[nt][0] = *(const uint32_t*)&Bt[b][c0][qp * 2];                      \
        bf[nt][1] = *(const uint32_t*)&Bt[b][c0][qp * 2 + 8];                  \
    }                                                                          \
    _Pragma("unroll")                                                          \
    for (int mt = 0; mt < 2; mt++)                                             \
        _Pragma("unroll")                                                      \
        for (int nt = 0; nt < 4; nt++)                                         \
            mma_f16(acc[mt][nt], af[mt][0], af[mt][1], af[mt][2], af[mt][3],   \
                    bf[nt][0], bf[nt][1]);                                     \
    } while (0)

    LOAD_B(0, 0);
    LOAD_B(1, 1);
    LOAD_A(0);
    __syncthreads();                 // publish sc/sh before STS_A uses them
    STS_A(0, 0); LOAD_A(1);
    cp_wait<1>(); __syncthreads();
    for (int kt = 0; kt < 16; kt++) {
        int b = kt & 1;
        if (kt + 1 < 16) STS_A(b ^ 1, kt + 1);
        if (kt + 2 < 16) LOAD_A(kt + 2);
        COMPUTE(b);
        if (kt + 1 < 16) cp_wait<0>();
        __syncthreads();
        if (kt + 2 < 16) LOAD_B(kt + 2, b);
    }
#undef LOAD_A
#undef STS_A
#undef LOAD_B
#undef COMPUTE

#pragma unroll
    for (int mt = 0; mt < 2; mt++) {
#pragma unroll
        for (int nt = 0; nt < 4; nt++) {
            int col = colBase + wn + nt * 8 + qp * 2;
            float b0 = b2[col], b1 = b2[col + 1];
            int gr0 = rowBase + wm + mt * 16 + grp;
            if (gr0 < n) {
                float2 xr = *(const float2*)&x[(size_t)gr0 * CH + col];
                *(float2*)&out[(size_t)gr0 * CH + col] =
                    make_float2(acc[mt][nt][0] + b0 + xr.x, acc[mt][nt][1] + b1 + xr.y);
            }
            int gr1 = gr0 + 8;
            if (gr1 < n) {
                float2 xr = *(const float2*)&x[(size_t)gr1 * CH + col];
                *(float2*)&out[(size_t)gr1 * CH + col] =
                    make_float2(acc[mt][nt][2] + b0 + xr.x, acc[mt][nt][3] + b1 + xr.y);
            }
        }
    }
}

// ---------------------------------------------------------------------------
extern "C" void kernel_launch(void* const* d_in, const int* in_sizes, int n_in,
                              void* d_out, int out_size) {
    const float* x     = (const float*)d_in[0];
    const float* Wl    = (const float*)d_in[1];
    const float* bl    = (const float*)d_in[2];
    const float* Wc    = (const float*)d_in[3];
    const float* gamma = (const float*)d_in[4];
    const float* beta  = (const float*)d_in[5];
    const float* W2    = (const float*)d_in[6];
    const float* b2    = (const float*)d_in[7];
    const int* in_idx  = (const int*)d_in[8];
    const int* out_idx = (const int*)d_in[9];
    float* out = (float*)d_out;

    int n = in_sizes[0] / CH;                 // 200000
    int M = in_sizes[8] / NPK;                // max pairs per (p,k)

    void* pS = nullptr; void* pQ = nullptr;
    cudaGetSymbolAddress(&pS, g_sum);
    cudaGetSymbolAddress(&pQ, g_sumsq);
    cudaMemsetAsync(pS, 0, CH * sizeof(float));
    cudaMemsetAsync(pQ, 0, CH * sizeof(float));

    prep_weights<<<2240, 256>>>(Wl, W2, Wc);
    count_pairs<<<1, 128>>>(in_idx, n, M);
    gemm_h<<<dim3(4, (n + 127) / 128), 256>>>(x, bl, n);
    conv_center<<<dim3((n + 127) / 128, PATHS), 256>>>(n);
    conv_scatter<<<dim3(CS_TILES, KOFF - 1, PATHS), 256>>>(in_idx, out_idx, M);
    bn_stats<<<1536, 256>>>(n);
    bn_finalize<<<1, 256>>>(gamma, beta, n);
    gemm_out<<<dim3(4, (n + 127) / 128), 256>>>(b2, x, out, n);
}

// round 15
// speedup vs baseline: 1.2818x; 1.2818x over previous
#include <cuda_runtime.h>
#include <cuda_fp16.h>
#include <cstdint>

#define CH 256
#define NMAX 200000
#define KOFF 27
#define PATHS 4
#define NPK (KOFF * PATHS)
#define CS_TILES 175   // >= ceil(max non-center cnt / 128); loop handles overflow

// Scratch (device globals: no allocation allowed in kernel_launch)
__device__ __half g_H16[(size_t)NMAX * CH];  // lifted features, fp16
__device__ __half g_A16[(size_t)NMAX * CH];  // conv result, fp16
__device__ float g_sum[CH];
__device__ float g_sumsq[CH];
__device__ float g_scale[CH];
__device__ float g_shift[CH];
__device__ __half g_Wlh[65536];              // Wl fp16, transposed [n=p*64+d][k=c]
__device__ __half g_W2h[65536];              // W2 fp16, transposed [n][k]
__device__ __half g_Wch[442368];             // Wc fp16, transposed [pk][d][c]
__device__ int   g_cnt[NPK];                 // valid pair count per (p,k)

// ---------------------------------------------------------------------------
// fp16 MMA, fp32 accumulate: A row-major 16x16, B col-major 16x8
__device__ __forceinline__ void mma_f16(float c[4], uint32_t a0, uint32_t a1,
                                        uint32_t a2, uint32_t a3,
                                        uint32_t b0, uint32_t b1) {
    asm volatile(
        "mma.sync.aligned.m16n8k16.row.col.f32.f16.f16.f32 "
        "{%0,%1,%2,%3}, {%4,%5,%6,%7}, {%8,%9}, {%0,%1,%2,%3};\n"
        : "+f"(c[0]), "+f"(c[1]), "+f"(c[2]), "+f"(c[3])
        : "r"(a0), "r"(a1), "r"(a2), "r"(a3), "r"(b0), "r"(b1));
}

__device__ __forceinline__ uint32_t smem_u32(const void* p) {
    return (uint32_t)__cvta_generic_to_shared(p);
}
__device__ __forceinline__ void cp16(uint32_t dst, const void* src, int sz) {
    asm volatile("cp.async.cg.shared.global [%0], [%1], 16, %2;"
                 :: "r"(dst), "l"(src), "r"(sz));
}
__device__ __forceinline__ void cp_commit() { asm volatile("cp.async.commit_group;"); }
template <int N> __device__ __forceinline__ void cp_wait() {
    asm volatile("cp.async.wait_group %0;" :: "n"(N));
}
// 4-half atomic add (8B): two packed f16x2 lanes
__device__ __forceinline__ void red_v2h2(__half* dst, uint32_t a, uint32_t b) {
    asm volatile("red.global.add.noftz.v2.f16x2 [%0], {%1,%2};"
                 :: "l"(dst), "r"(a), "r"(b) : "memory");
}
__device__ __forceinline__ uint32_t pack_h2(float a, float b) {
    __half2 h = __floats2half2_rn(a, b);
    return *(uint32_t*)&h;
}

// ---------------------------------------------------------------------------
__global__ void prep_weights(const float* __restrict__ Wl,
                             const float* __restrict__ W2,
                             const float* __restrict__ Wc) {
    int i = blockIdx.x * 256 + threadIdx.x;
    if (i < 65536) {
        // Wl [P][256][64] -> g_Wlh [n=p*64+d][k=c]
        int p = i >> 14, c = (i >> 6) & 255, d = i & 63;
        g_Wlh[(p * 64 + d) * 256 + c] = __float2half(Wl[i]);
    } else if (i < 131072) {
        // W2 [256][256] (k,n) -> g_W2h [n][k]
        int j = i - 65536;
        int k = j >> 8, nn = j & 255;
        g_W2h[nn * 256 + k] = __float2half(W2[j]);
    } else if (i < 131072 + 442368) {
        int j = i - 131072;
        int pk = j >> 12, r = j & 4095, d = r >> 6, c = r & 63;
        g_Wch[j] = __float2half(Wc[(size_t)pk * 4096 + c * 64 + d]);  // transpose
    }
}

// Valid pairs per (p,k) are a prefix -> binary search the boundary.
__global__ void count_pairs(const int* __restrict__ in_idx, int n, int M) {
    int pk = threadIdx.x;
    if (pk >= NPK) return;
    const int* a = in_idx + (size_t)pk * M;
    int lo = 0, hi = M;
    while (lo < hi) {
        int mid = (lo + hi) >> 1;
        if (__ldg(&a[mid]) < n) lo = mid + 1; else hi = mid;
    }
    g_cnt[pk] = lo;
}

// ---------------------------------------------------------------------------
// H = fp16round(x @ Wl_cat + bl).  fp16 MMA m16n8k16; tile 128x128, BK=16,
// 2-stage cp.async pipeline.  (R13 form.)
__global__ __launch_bounds__(256) void gemm_h(const float* __restrict__ x,
                                              const float* __restrict__ bl, int n) {
    __shared__ __align__(16) __half As[2][128][24];   // [m][k]
    __shared__ __align__(16) __half Bt[2][128][24];   // [n][k]
    const int colBase = blockIdx.x * 128;
    const int rowBase = blockIdx.y * 128;
    const int tid = threadIdx.x;
    const int warpId = tid >> 5, lane = tid & 31;
    const int grp = lane >> 2, qp = lane & 3;
    const int wm = (warpId & 3) * 32, wn = (warpId >> 2) * 64;

    float acc[2][8][4];
#pragma unroll
    for (int mt = 0; mt < 2; mt++)
#pragma unroll
        for (int nt = 0; nt < 8; nt++)
#pragma unroll
            for (int r = 0; r < 4; r++) acc[mt][nt][r] = 0.f;

    float4 ar[2];
    int arow[2], akq[2];
#pragma unroll
    for (int i = 0; i < 2; i++) { int ci = tid + i * 256; arow[i] = ci >> 2; akq[i] = ci & 3; }

#define LOAD_A(kt) do {                                                        \
    _Pragma("unroll")                                                          \
    for (int i = 0; i < 2; i++) {                                              \
        int gr = rowBase + arow[i];                                            \
        ar[i] = (gr < n) ? *(const float4*)&x[(size_t)gr * CH + (kt) * 16 + akq[i] * 4] \
                         : make_float4(0.f, 0.f, 0.f, 0.f);                    \
    } } while (0)
#define STS_A(b) do {                                                          \
    _Pragma("unroll")                                                          \
    for (int i = 0; i < 2; i++) {                                              \
        float4 v = ar[i];                                                      \
        *(__half2*)&As[b][arow[i]][akq[i] * 4]     = __floats2half2_rn(v.x, v.y); \
        *(__half2*)&As[b][arow[i]][akq[i] * 4 + 2] = __floats2half2_rn(v.z, v.w); \
    } } while (0)
#define LOAD_B(kt, b) do {                                                     \
    int col_ = tid >> 1, q_ = tid & 1;                                         \
    cp16(smem_u32(&Bt[b][col_][q_ * 8]),                                       \
         &g_Wlh[(size_t)(colBase + col_) * 256 + (kt) * 16 + q_ * 8], 16);     \
    cp_commit(); } while (0)
#define COMPUTE(b) do {                                                        \
    uint32_t af[2][4], bf[8][2];                                               \
    _Pragma("unroll")                                                          \
    for (int mt = 0; mt < 2; mt++) {                                           \
        int r0 = wm + mt * 16 + grp;                                           \
        af[mt][0] = *(const uint32_t*)&As[b][r0][qp * 2];                      \
        af[mt][1] = *(const uint32_t*)&As[b][r0 + 8][qp * 2];                  \
        af[mt][2] = *(const uint32_t*)&As[b][r0][qp * 2 + 8];                  \
        af[mt][3] = *(const uint32_t*)&As[b][r0 + 8][qp * 2 + 8];              \
    }                                                                          \
    _Pragma("unroll")                                                          \
    for (int nt = 0; nt < 8; nt++) {                                           \
        int c0 = wn + nt * 8 + grp;                                            \
        bf[nt][0] = *(const uint32_t*)&Bt[b][c0][qp * 2];                      \
        bf[nt][1] = *(const uint32_t*)&Bt[b][c0][qp * 2 + 8];                  \
    }                                                                          \
    _Pragma("unroll")                                                          \
    for (int mt = 0; mt < 2; mt++)                                             \
        _Pragma("unroll")                                                      \
        for (int nt = 0; nt < 8; nt++)                                         \
            mma_f16(acc[mt][nt], af[mt][0], af[mt][1], af[mt][2], af[mt][3],   \
                    bf[nt][0], bf[nt][1]);                                     \
    } while (0)

    LOAD_B(0, 0);
    LOAD_B(1, 1);
    LOAD_A(0); STS_A(0); LOAD_A(1);
    cp_wait<1>(); __syncthreads();
    for (int kt = 0; kt < 16; kt++) {
        int b = kt & 1;
        if (kt + 1 < 16) STS_A(b ^ 1);
        if (kt + 2 < 16) LOAD_A(kt + 2);
        COMPUTE(b);
        if (kt + 1 < 16) cp_wait<0>();
        __syncthreads();
        if (kt + 2 < 16) LOAD_B(kt + 2, b);
    }
#undef LOAD_A
#undef STS_A
#undef LOAD_B
#undef COMPUTE

#pragma unroll
    for (int mt = 0; mt < 2; mt++) {
#pragma unroll
        for (int nt = 0; nt < 8; nt++) {
            int col = colBase + wn + nt * 8 + qp * 2;
            float b0 = bl[col], b1 = bl[col + 1];
            int gr0 = rowBase + wm + mt * 16 + grp;
            if (gr0 < n) {
                __half2 h = __floats2half2_rn(acc[mt][nt][0] + b0, acc[mt][nt][1] + b1);
                *(__half2*)&g_H16[(size_t)gr0 * CH + col] = h;
            }
            int gr1 = gr0 + 8;
            if (gr1 < n) {
                __half2 h = __floats2half2_rn(acc[mt][nt][2] + b0, acc[mt][nt][3] + b1);
                *(__half2*)&g_H16[(size_t)gr1 * CH + col] = h;
            }
        }
    }
}

// ---------------------------------------------------------------------------
// Center offset (k=13): identity pairs, covers ALL rows.  fp16 gather +
// fp16 MMA, fp32 staging, fp16 coalesced stores (initializes g_A16).
__global__ __launch_bounds__(256) void conv_center(int n) {
    __shared__ __align__(16) char sm[32768];
    __half (*Gs)[72] = (__half(*)[72])sm;            // [128][72] halves
    __half (*Wt)[72] = (__half(*)[72])(sm + 18432);  // [64][72] halves (transposed W)
    float* Stg = (float*)sm;                         // phase 2: [128][64] floats
    const int p = blockIdx.y;
    const int r0b = blockIdx.x * 128;
    const int tid = threadIdx.x;

    {   // weights: 64 rows x 128B
        const __half* Wpk = g_Wch + (size_t)(p * KOFF + 13) * 4096;
#pragma unroll
        for (int i = 0; i < 2; i++) {
            int ci = tid + i * 256;
            int d = ci >> 3, q = ci & 7;
            cp16(smem_u32(&Wt[d][q * 8]), &Wpk[d * 64 + q * 8], 16);
        }
    }
    {   // gather (identity): 128 rows x 128B
        int m = tid >> 1, half_ = tid & 1;
        int gr = r0b + m;
        int sz = (gr < n) ? 16 : 0;
        const __half* hp = &g_H16[(size_t)(gr < n ? gr : 0) * CH + p * 64 + half_ * 32];
#pragma unroll
        for (int q = 0; q < 4; q++)
            cp16(smem_u32(&Gs[m][half_ * 32 + q * 8]), hp + q * 8, sz);
    }
    cp_commit(); cp_wait<0>(); __syncthreads();

    const int warpId = tid >> 5, lane = tid & 31;
    const int grp = lane >> 2, qp = lane & 3;
    const int wm = (warpId & 3) * 32, wn = (warpId >> 2) * 32;

    float acc[2][4][4];
#pragma unroll
    for (int mt = 0; mt < 2; mt++)
#pragma unroll
        for (int nt = 0; nt < 4; nt++)
#pragma unroll
            for (int r = 0; r < 4; r++) acc[mt][nt][r] = 0.f;

#pragma unroll
    for (int c8 = 0; c8 < 4; c8++) {
        int kk0 = c8 * 16;
        uint32_t af[2][4], bf[4][2];
#pragma unroll
        for (int mt = 0; mt < 2; mt++) {
            int r = wm + mt * 16 + grp;
            af[mt][0] = *(const uint32_t*)&Gs[r][kk0 + qp * 2];
            af[mt][1] = *(const uint32_t*)&Gs[r + 8][kk0 + qp * 2];
            af[mt][2] = *(const uint32_t*)&Gs[r][kk0 + qp * 2 + 8];
            af[mt][3] = *(const uint32_t*)&Gs[r + 8][kk0 + qp * 2 + 8];
        }
#pragma unroll
        for (int nt = 0; nt < 4; nt++) {
            int c0 = wn + nt * 8 + grp;
            bf[nt][0] = *(const uint32_t*)&Wt[c0][kk0 + qp * 2];
            bf[nt][1] = *(const uint32_t*)&Wt[c0][kk0 + qp * 2 + 8];
        }
#pragma unroll
        for (int mt = 0; mt < 2; mt++)
#pragma unroll
            for (int nt = 0; nt < 4; nt++)
                mma_f16(acc[mt][nt], af[mt][0], af[mt][1], af[mt][2], af[mt][3],
                        bf[nt][0], bf[nt][1]);
    }
    __syncthreads();                 // Gs/Wt dead -> reuse as Stg

#pragma unroll
    for (int mt = 0; mt < 2; mt++)
#pragma unroll
        for (int nt = 0; nt < 4; nt++) {
            int col = wn + nt * 8 + qp * 2;
            int rw = wm + mt * 16 + grp;
            int sw = (rw & 7) << 2;  // same for rw and rw+8
            *(float2*)&Stg[rw * 64 + (col ^ sw)] =
                make_float2(acc[mt][nt][0], acc[mt][nt][1]);
            *(float2*)&Stg[(rw + 8) * 64 + (col ^ sw)] =
                make_float2(acc[mt][nt][2], acc[mt][nt][3]);
        }
    __syncthreads();

#pragma unroll
    for (int i = 0; i < 4; i++) {
        int idx = tid + i * 256;
        int row = idx >> 3, g8 = idx & 7;
        int gr = r0b + row;
        if (gr < n) {
            int sw = (row & 7) << 2;
            float4 v0 = *(const float4*)&Stg[row * 64 + ((g8 * 8) ^ sw)];
            float4 v1 = *(const float4*)&Stg[row * 64 + ((g8 * 8 + 4) ^ sw)];
            __half2 h[4];
            h[0] = __floats2half2_rn(v0.x, v0.y);
            h[1] = __floats2half2_rn(v0.z, v0.w);
            h[2] = __floats2half2_rn(v1.x, v1.y);
            h[3] = __floats2half2_rn(v1.z, v1.w);
            *(uint4*)&g_A16[(size_t)gr * CH + p * 64 + g8 * 8] = *(uint4*)h;
        }
    }
}

// ---------------------------------------------------------------------------
// Sparse conv over the 26 non-center offsets: fp16 gather + fp16 MMA,
// lane-pair shuffle -> red.global.add.noftz.v2.f16x2 scatter.
__global__ __launch_bounds__(256) void conv_scatter(const int* __restrict__ in_idx,
                                                    const int* __restrict__ out_idx,
                                                    int M) {
    __shared__ __align__(16) __half Gs[128][72];
    __shared__ __align__(16) __half Wt[64][72];
    __shared__ int Os[128];
    const int p = blockIdx.z;
    const int ky = blockIdx.y;
    const int k = ky + (ky >= 13);  // skip center
    const int pk = p * KOFF + k;
    const int cnt = g_cnt[pk];
    const int tid = threadIdx.x;
    if (blockIdx.x * 128 >= cnt) return;

    {   // weights once per block (joins first gather's commit group)
        const __half* Wpk = g_Wch + (size_t)pk * 4096;
#pragma unroll
        for (int i = 0; i < 2; i++) {
            int ci = tid + i * 256;
            int d = ci >> 3, q = ci & 7;
            cp16(smem_u32(&Wt[d][q * 8]), &Wpk[d * 64 + q * 8], 16);
        }
    }

    const int warpId = tid >> 5, lane = tid & 31;
    const int grp = lane >> 2, qp = lane & 3;
    const int wm = (warpId & 3) * 32, wn = (warpId >> 2) * 32;

    for (int base0 = blockIdx.x * 128; base0 < cnt; base0 += gridDim.x * 128) {
        int rem = cnt - base0; if (rem > 128) rem = 128;
        const size_t base = (size_t)pk * M + base0;

        {
            int m = tid >> 1, half_ = tid & 1;
            int jm = (m < rem) ? __ldg(&in_idx[base + m]) : 0;
            int sz = (m < rem) ? 16 : 0;   // sz=0 -> cp.async zero-fills
            const __half* hp = &g_H16[(size_t)jm * CH + p * 64 + half_ * 32];
#pragma unroll
            for (int q = 0; q < 4; q++)
                cp16(smem_u32(&Gs[m][half_ * 32 + q * 8]), hp + q * 8, sz);
            if (half_ == 0)
                Os[m] = (m < rem) ? __ldg(&out_idx[base + m]) : -1;
        }
        cp_commit(); cp_wait<0>(); __syncthreads();

        float acc[2][4][4];
#pragma unroll
        for (int mt = 0; mt < 2; mt++)
#pragma unroll
            for (int nt = 0; nt < 4; nt++)
#pragma unroll
                for (int r = 0; r < 4; r++) acc[mt][nt][r] = 0.f;

#pragma unroll
        for (int c8 = 0; c8 < 4; c8++) {
            int kk0 = c8 * 16;
            uint32_t af[2][4], bf[4][2];
#pragma unroll
            for (int mt = 0; mt < 2; mt++) {
                int r = wm + mt * 16 + grp;
                af[mt][0] = *(const uint32_t*)&Gs[r][kk0 + qp * 2];
                af[mt][1] = *(const uint32_t*)&Gs[r + 8][kk0 + qp * 2];
                af[mt][2] = *(const uint32_t*)&Gs[r][kk0 + qp * 2 + 8];
                af[mt][3] = *(const uint32_t*)&Gs[r + 8][kk0 + qp * 2 + 8];
            }
#pragma unroll
            for (int nt = 0; nt < 4; nt++) {
                int c0 = wn + nt * 8 + grp;
                bf[nt][0] = *(const uint32_t*)&Wt[c0][kk0 + qp * 2];
                bf[nt][1] = *(const uint32_t*)&Wt[c0][kk0 + qp * 2 + 8];
            }
#pragma unroll
            for (int mt = 0; mt < 2; mt++)
#pragma unroll
                for (int nt = 0; nt < 4; nt++)
                    mma_f16(acc[mt][nt], af[mt][0], af[mt][1], af[mt][2], af[mt][3],
                            bf[nt][0], bf[nt][1]);
        }

        // Lane-pair shuffle -> 4-half RED scatter (even-qp lanes issue)
#pragma unroll
        for (int mt = 0; mt < 2; mt++) {
            int r = wm + mt * 16 + grp;
            int o0 = Os[r], o1 = Os[r + 8];
#pragma unroll
            for (int nt = 0; nt < 4; nt++) {
                float a0 = acc[mt][nt][0], a1 = acc[mt][nt][1];
                float a2 = acc[mt][nt][2], a3 = acc[mt][nt][3];
                float p0 = __shfl_xor_sync(0xffffffffu, a0, 1);
                float p1 = __shfl_xor_sync(0xffffffffu, a1, 1);
                float p2 = __shfl_xor_sync(0xffffffffu, a2, 1);
                float p3 = __shfl_xor_sync(0xffffffffu, a3, 1);
                if ((qp & 1) == 0) {
                    int col = p * 64 + wn + nt * 8 + qp * 2;  // 8B-aligned
                    if (o0 >= 0)
                        red_v2h2(&g_A16[(size_t)o0 * CH + col],
                                 pack_h2(a0, a1), pack_h2(p0, p1));
                    if (o1 >= 0)
                        red_v2h2(&g_A16[(size_t)o1 * CH + col],
                                 pack_h2(a2, a3), pack_h2(p2, p3));
                }
            }
        }
        __syncthreads();            // Gs/Os reusable for next tile
    }
}

// ---------------------------------------------------------------------------
// Per-channel sum/sumsq over fp16 g_A16: 8 row-lanes x 32 ch-groups (8ch each)
__global__ __launch_bounds__(256) void bn_stats(int n) {
    __shared__ float rs[8][256], rq[8][256];
    int tid = threadIdx.x;
    int cg = tid & 31;              // channel group (8 ch)
    int rl = tid >> 5;              // row lane 0..7
    float s[8], s2[8];
#pragma unroll
    for (int j = 0; j < 8; j++) { s[j] = 0.f; s2[j] = 0.f; }
    for (int r = blockIdx.x * 8 + rl; r < n; r += gridDim.x * 8) {
        uint4 u = *(const uint4*)&g_A16[(size_t)r * CH + cg * 8];
        __half2* hp = (__half2*)&u;
#pragma unroll
        for (int j = 0; j < 4; j++) {
            float2 f = __half22float2(hp[j]);
            s[2 * j] += f.x;  s2[2 * j] += f.x * f.x;
            s[2 * j + 1] += f.y; s2[2 * j + 1] += f.y * f.y;
        }
    }
#pragma unroll
    for (int j = 0; j < 8; j++) {
        rs[rl][cg * 8 + j] = s[j];
        rq[rl][cg * 8 + j] = s2[j];
    }
    __syncthreads();
    float S = 0.f, Q = 0.f;
#pragma unroll
    for (int l = 0; l < 8; l++) { S += rs[l][tid]; Q += rq[l][tid]; }
    atomicAdd(&g_sum[tid], S);
    atomicAdd(&g_sumsq[tid], Q);
}

__global__ void bn_finalize(const float* __restrict__ gamma,
                            const float* __restrict__ beta, int n) {
    int j = threadIdx.x;
    float inv = 1.f / (float)n;
    float mu = g_sum[j] * inv;
    float var = g_sumsq[j] * inv - mu * mu;
    float sc = gamma[j] * rsqrtf(var + 1e-5f);
    g_scale[j] = sc;
    g_shift[j] = beta[j] - mu * sc;
}

// ---------------------------------------------------------------------------
// out = relu(bn(A16)) @ W2 + b2 + x.  fp16 MMA; tile 128x128 (R13 shape);
// bn+relu fused into fp16 A staging (uint4 = 8 ch per thread per stage).
__global__ __launch_bounds__(256) void gemm_out(const float* __restrict__ b2,
                                                const float* __restrict__ x,
                                                float* __restrict__ out, int n) {
    __shared__ __align__(16) __half As[2][128][24];
    __shared__ __align__(16) __half Bt[2][128][24];
    __shared__ float sc[256], sh[256];
    const int colBase = blockIdx.x * 128;
    const int rowBase = blockIdx.y * 128;
    const int tid = threadIdx.x;
    const int warpId = tid >> 5, lane = tid & 31;
    const int grp = lane >> 2, qp = lane & 3;
    const int wm = (warpId & 3) * 32, wn = (warpId >> 2) * 64;

    sc[tid] = g_scale[tid];
    sh[tid] = g_shift[tid];

    float acc[2][8][4];
#pragma unroll
    for (int mt = 0; mt < 2; mt++)
#pragma unroll
        for (int nt = 0; nt < 8; nt++)
#pragma unroll
            for (int r = 0; r < 4; r++) acc[mt][nt][r] = 0.f;

    uint4 au;
    const int arow = tid >> 1, ahg = tid & 1;   // 128 rows x 2 half-groups(8ch)

#define LOAD_A(kt) do {                                                        \
    int gr = rowBase + arow;                                                   \
    au = (gr < n) ? *(const uint4*)&g_A16[(size_t)gr * CH + (kt) * 16 + ahg * 8] \
                  : make_uint4(0u, 0u, 0u, 0u);                                \
    } while (0)
#define STS_A(b, kt) do {                                                      \
    __half2* hp_ = (__half2*)&au;                                              \
    int c0 = (kt) * 16 + ahg * 8;                                              \
    __half2 o_[4];                                                             \
    _Pragma("unroll")                                                          \
    for (int j = 0; j < 4; j++) {                                              \
        float2 f = __half22float2(hp_[j]);                                     \
        f.x = fmaxf(f.x * sc[c0 + 2 * j] + sh[c0 + 2 * j], 0.f);               \
        f.y = fmaxf(f.y * sc[c0 + 2 * j + 1] + sh[c0 + 2 * j + 1], 0.f);       \
        o_[j] = __floats2half2_rn(f.x, f.y);                                   \
    }                                                                          \
    *(uint4*)&As[b][arow][ahg * 8] = *(uint4*)o_;                              \
    } while (0)
#define LOAD_B(kt, b) do {                                                     \
    int col_ = tid >> 1, q_ = tid & 1;                                         \
    cp16(smem_u32(&Bt[b][col_][q_ * 8]),                                       \
         &g_W2h[(size_t)(colBase + col_) * 256 + (kt) * 16 + q_ * 8], 16);     \
    cp_commit(); } while (0)
#define COMPUTE(b) do {                                                        \
    uint32_t af[2][4], bf[8][2];                                               \
    _Pragma("unroll")                                                          \
    for (int mt = 0; mt < 2; mt++) {                                           \
        int r0 = wm + mt * 16 + grp;                                           \
        af[mt][0] = *(const uint32_t*)&As[b][r0][qp * 2];                      \
        af[mt][1] = *(const uint32_t*)&As[b][r0 + 8][qp * 2];                  \
        af[mt][2] = *(const uint32_t*)&As[b][r0][qp * 2 + 8];                  \
        af[mt][3] = *(const uint32_t*)&As[b][r0 + 8][qp * 2 + 8];              \
    }                                                                          \
    _Pragma("unroll")                                                          \
    for (int nt = 0; nt < 8; nt++) {                                           \
        int c0 = wn + nt * 8 + grp;                                            \
        bf[nt][0] = *(const uint32_t*)&Bt[b][c0][qp * 2];                      \
        bf[nt][1] = *(const uint32_t*)&Bt[b][c0][qp * 2 + 8];                  \
    }                                                                          \
    _Pragma("unroll")                                                          \
    for (int mt = 0; mt < 2; mt++)                                             \
        _Pragma("unroll")                                                      \
        for (int nt = 0; nt < 8; nt++)                                         \
            mma_f16(acc[mt][nt], af[mt][0], af[mt][1], af[mt][2], af[mt][3],   \
                    bf[nt][0], bf[nt][1]);                                     \
    } while (0)

    LOAD_B(0, 0);
    LOAD_B(1, 1);
    LOAD_A(0);
    __syncthreads();                 // publish sc/sh before STS_A uses them
    STS_A(0, 0); LOAD_A(1);
    cp_wait<1>(); __syncthreads();
    for (int kt = 0; kt < 16; kt++) {
        int b = kt & 1;
        if (kt + 1 < 16) STS_A(b ^ 1, kt + 1);
        if (kt + 2 < 16) LOAD_A(kt + 2);
        COMPUTE(b);
        if (kt + 1 < 16) cp_wait<0>();
        __syncthreads();
        if (kt + 2 < 16) LOAD_B(kt + 2, b);
    }
#undef LOAD_A
#undef STS_A
#undef LOAD_B
#undef COMPUTE

#pragma unroll
    for (int mt = 0; mt < 2; mt++) {
#pragma unroll
        for (int nt = 0; nt < 8; nt++) {
            int col = colBase + wn + nt * 8 + qp * 2;
            float b0 = b2[col], b1 = b2[col + 1];
            int gr0 = rowBase + wm + mt * 16 + grp;
            if (gr0 < n) {
                float2 xr = *(const float2*)&x[(size_t)gr0 * CH + col];
                *(float2*)&out[(size_t)gr0 * CH + col] =
                    make_float2(acc[mt][nt][0] + b0 + xr.x, acc[mt][nt][1] + b1 + xr.y);
            }
            int gr1 = gr0 + 8;
            if (gr1 < n) {
                float2 xr = *(const float2*)&x[(size_t)gr1 * CH + col];
                *(float2*)&out[(size_t)gr1 * CH + col] =
                    make_float2(acc[mt][nt][2] + b0 + xr.x, acc[mt][nt][3] + b1 + xr.y);
            }
        }
    }
}

// ---------------------------------------------------------------------------
extern "C" void kernel_launch(void* const* d_in, const int* in_sizes, int n_in,
                              void* d_out, int out_size) {
    const float* x     = (const float*)d_in[0];
    const float* Wl    = (const float*)d_in[1];
    const float* bl    = (const float*)d_in[2];
    const float* Wc    = (const float*)d_in[3];
    const float* gamma = (const float*)d_in[4];
    const float* beta  = (const float*)d_in[5];
    const float* W2    = (const float*)d_in[6];
    const float* b2    = (const float*)d_in[7];
    const int* in_idx  = (const int*)d_in[8];
    const int* out_idx = (const int*)d_in[9];
    float* out = (float*)d_out;

    int n = in_sizes[0] / CH;                 // 200000
    int M = in_sizes[8] / NPK;                // max pairs per (p,k)

    void* pS = nullptr; void* pQ = nullptr;
    cudaGetSymbolAddress(&pS, g_sum);
    cudaGetSymbolAddress(&pQ, g_sumsq);
    cudaMemsetAsync(pS, 0, CH * sizeof(float));
    cudaMemsetAsync(pQ, 0, CH * sizeof(float));

    prep_weights<<<2240, 256>>>(Wl, W2, Wc);
    count_pairs<<<1, 128>>>(in_idx, n, M);
    gemm_h<<<dim3(2, (n + 127) / 128), 256>>>(x, bl, n);
    conv_center<<<dim3((n + 127) / 128, PATHS), 256>>>(n);
    conv_scatter<<<dim3(CS_TILES, KOFF - 1, PATHS), 256>>>(in_idx, out_idx, M);
    bn_stats<<<1536, 256>>>(n);
    bn_finalize<<<1, 256>>>(gamma, beta, n);
    gemm_out<<<dim3(2, (n + 127) / 128), 256>>>(b2, x, out, n);
}